// round 1
// baseline (speedup 1.0000x reference)
#include <cuda_runtime.h>

// actions: [B=4096, T=256, A=64] fp32
// out[b,t,a] = x[b,0,a] + sum_{s=1..t} clip(x[b,s,a]-x[b,s-1,a], -0.5, 0.5)
//
// One thread owns one (b, a4) chain of 256 timesteps, processed as float4.
// A-dim = 64 floats = 16 float4; t-stride = 16 float4; b-stride = 4096 float4.
// Loads within a chunk are independent (increments depend only on inputs),
// so we batch 8 loads per chunk for MLP ~8.

#define TSTEPS 256
#define TSTRIDE 16   // float4 elements between consecutive t

__device__ __forceinline__ float clip05(float d) {
    return fminf(fmaxf(d, -0.5f), 0.5f);
}

__global__ void __launch_bounds__(256) smoothness_kernel(
    const float4* __restrict__ x, float4* __restrict__ y)
{
    int idx = blockIdx.x * blockDim.x + threadIdx.x;   // 0 .. 65535
    // chain base: b = idx>>4 (a-dim has 16 float4), a4 = idx & 15
    long base = (long)(idx >> 4) * (TSTEPS * TSTRIDE) + (idx & 15);
    const float4* xp = x + base;
    float4*       yp = y + base;

    float4 prev = xp[0];
    float4 acc  = prev;
    yp[0] = acc;

    int t = 1;
    // chunks of 8: loads batched first for memory-level parallelism
    for (; t + 8 <= TSTEPS; t += 8) {
        float4 c[8];
        #pragma unroll
        for (int j = 0; j < 8; ++j)
            c[j] = xp[(t + j) * TSTRIDE];
        #pragma unroll
        for (int j = 0; j < 8; ++j) {
            acc.x += clip05(c[j].x - prev.x);
            acc.y += clip05(c[j].y - prev.y);
            acc.z += clip05(c[j].z - prev.z);
            acc.w += clip05(c[j].w - prev.w);
            prev = c[j];
            yp[(t + j) * TSTRIDE] = acc;
        }
    }
    // remainder (t = 249..255)
    for (; t < TSTEPS; ++t) {
        float4 c = xp[t * TSTRIDE];
        acc.x += clip05(c.x - prev.x);
        acc.y += clip05(c.y - prev.y);
        acc.z += clip05(c.z - prev.z);
        acc.w += clip05(c.w - prev.w);
        prev = c;
        yp[t * TSTRIDE] = acc;
    }
}

extern "C" void kernel_launch(void* const* d_in, const int* in_sizes, int n_in,
                              void* d_out, int out_size) {
    const float4* x = (const float4*)d_in[0];
    float4* y = (float4*)d_out;
    // total chains in float4 units: 4096 * 16 = 65536
    int threads = 65536;
    smoothness_kernel<<<threads / 256, 256>>>(x, y);
}

// round 2
// speedup vs baseline: 1.2980x; 1.2980x over previous
#include <cuda_runtime.h>

// actions: [B=4096, T=256, A=64] fp32
// out[b,t,a] = x[b,0,a] + sum_{s=1..t} clip(x[b,s,a]-x[b,s-1,a], -0.5, 0.5)
//
// Block-local segmented scan: 1 block per b. 256 threads = 16 t-segments x 16
// a4-columns (A=64 floats = 16 float4). Each thread scans its 16-timestep
// segment locally in registers, segment totals are combined via smem, then
// the global offset is added and results stored. Exactly 1 load + 1 store
// per element (+1 boundary float4 per segment).

#define A4     16   // float4 per A-dim
#define SEGS   16
#define SEGLEN 16
#define TSTEPS 256

__device__ __forceinline__ float clip05(float d) {
    return fminf(fmaxf(d, -0.5f), 0.5f);
}

__device__ __forceinline__ float4 f4add(float4 a, float4 b) {
    return make_float4(a.x + b.x, a.y + b.y, a.z + b.z, a.w + b.w);
}

__global__ void __launch_bounds__(256, 2) smoothness_scan_kernel(
    const float4* __restrict__ x, float4* __restrict__ y)
{
    const int b   = blockIdx.x;
    const int tid = threadIdx.x;
    const int seg = tid >> 4;     // 0..15
    const int a4  = tid & 15;     // 0..15

    const float4* xb = x + (long)b * (TSTEPS * A4);
    float4*       yb = y + (long)b * (TSTEPS * A4);

    __shared__ float4 s_sum[SEGS][A4];   // per-segment clipped-diff totals
    __shared__ float4 s_x0[A4];          // x[b, 0, :]

    const int t0 = seg * SEGLEN;

    // Batch all loads up front for memory-level parallelism (~17 in flight).
    float4 c[SEGLEN];
    #pragma unroll
    for (int j = 0; j < SEGLEN; ++j)
        c[j] = xb[(t0 + j) * A4 + a4];

    float4 prev;
    if (seg > 0)
        prev = xb[(t0 - 1) * A4 + a4];   // boundary element (re-read, cheap)

    // Local prefix of clipped diffs within the segment, in-place into c[].
    float4 acc = make_float4(0.f, 0.f, 0.f, 0.f);
    int jstart = 0;
    if (seg == 0) {
        s_x0[a4] = c[0];
        prev = c[0];
        c[0] = acc;                      // local prefix at t=0 is 0
        jstart = 1;
    }
    #pragma unroll
    for (int j = 0; j < SEGLEN; ++j) {
        if (j < jstart) continue;
        float4 cur = c[j];
        acc.x += clip05(cur.x - prev.x);
        acc.y += clip05(cur.y - prev.y);
        acc.z += clip05(cur.z - prev.z);
        acc.w += clip05(cur.w - prev.w);
        prev = cur;
        c[j] = acc;
    }
    s_sum[seg][a4] = acc;
    __syncthreads();

    // Exclusive prefix over segment totals + base x[b,0,:].
    float4 offset = s_x0[a4];
    #pragma unroll
    for (int k = 0; k < SEGS; ++k) {
        if (k < seg) offset = f4add(offset, s_sum[k][a4]);
    }

    // Add offset and store.
    #pragma unroll
    for (int j = 0; j < SEGLEN; ++j)
        yb[(t0 + j) * A4 + a4] = f4add(offset, c[j]);
}

extern "C" void kernel_launch(void* const* d_in, const int* in_sizes, int n_in,
                              void* d_out, int out_size) {
    const float4* x = (const float4*)d_in[0];
    float4* y = (float4*)d_out;
    smoothness_scan_kernel<<<4096, 256>>>(x, y);
}